// round 1
// baseline (speedup 1.0000x reference)
#include <cuda_runtime.h>
#include <cuda_bf16.h>
#include <cstdint>
#include <cstdio>

// Problem constants
#define BATCH 2
#define SEQ   2048
#define DIM   1024
#define HEADS 16
#define HDIM  64
#define MROWS (BATCH * SEQ)          // 4096
#define BH    (BATCH * HEADS)        // 32

// ---------------- scratch (static __device__, no runtime alloc) ----------------
__device__ float g_Q[(size_t)MROWS * DIM];
__device__ float g_K[(size_t)MROWS * DIM];
__device__ float g_V[(size_t)MROWS * DIM];
__device__ float g_O[(size_t)MROWS * DIM];
__device__ float g_S[(size_t)BH * SEQ * SEQ];   // 512 MB scores buffer

// ---------------- tf32 helpers ----------------
__device__ __forceinline__ uint32_t f2tf(float f) {
    uint32_t u;
    asm("cvt.rna.tf32.f32 %0, %1;" : "=r"(u) : "f"(f));
    return u;
}

__device__ __forceinline__ void mma_tf32(float c[4], const uint32_t a[4], const uint32_t b[2]) {
    asm volatile(
        "mma.sync.aligned.m16n8k8.row.col.f32.tf32.tf32.f32 "
        "{%0,%1,%2,%3}, {%4,%5,%6,%7}, {%8,%9}, {%0,%1,%2,%3};\n"
        : "+f"(c[0]), "+f"(c[1]), "+f"(c[2]), "+f"(c[3])
        : "r"(a[0]), "r"(a[1]), "r"(a[2]), "r"(a[3]), "r"(b[0]), "r"(b[1]));
}

// ---------------- generic tf32 GEMM ----------------
// C[m][n] = alpha * sum_k A[m][k] * B(k,n)  (+ bias[n])
// A: row-major, lda.
// TRANSB == false: B stored as (n, k) with k contiguous (i.e. W[n][k]), ldb = row stride.
// TRANSB == true : B stored as (k, n) with n contiguous, ldb = row stride.
// Batch: z = blockIdx.z decomposed as zb = z>>4, zh = z&15; per-operand offsets.
// Requires: M % BM == 0, N % BN == 0, K % BK == 0 (guaranteed by launch configs).
template<int BM, int BN, int BK, bool TRANSB, bool HAS_BIAS>
__global__ void __launch_bounds__((BM / 64) * (BN / 32) * 32)
gemm_tf32(const float* __restrict__ A, const float* __restrict__ B, float* __restrict__ C,
          int Kdim, int lda, int ldb, int ldc,
          long long oAb, long long oAh, long long oBb, long long oBh,
          long long oCb, long long oCh,
          float alpha, const float* __restrict__ bias)
{
    constexpr int WN  = BN / 32;           // warps along n
    constexpr int WM  = BM / 64;           // warps along m
    constexpr int NTH = WM * WN * 32;

    const int z  = blockIdx.z;
    const int zb = z >> 4;
    const int zh = z & 15;
    const float* Ab = A + (size_t)zb * oAb + (size_t)zh * oAh;
    const float* Bb = B + (size_t)zb * oBb + (size_t)zh * oBh;
    float*       Cb = C + (size_t)zb * oCb + (size_t)zh * oCh;

    const int m0 = blockIdx.y * BM;
    const int n0 = blockIdx.x * BN;

    const int tid  = threadIdx.x;
    const int warp = tid >> 5;
    const int lane = tid & 31;
    const int g    = lane >> 2;   // group id (0..7)
    const int t    = lane & 3;    // thread-in-group (0..3)
    const int wm   = warp / WN;
    const int wn   = warp % WN;

    __shared__ float As[BM][BK + 4];
    __shared__ float Bs[BN][BK + 4];

    float acc[4][4][4] = {};      // [mfrag][nfrag][creg]

    for (int k0 = 0; k0 < Kdim; k0 += BK) {
        // ---- load A tile (BM x BK), float4 ----
        #pragma unroll
        for (int i = tid; i < BM * BK / 4; i += NTH) {
            int r  = i / (BK / 4);
            int c4 = (i % (BK / 4)) * 4;
            float4 v = *(const float4*)&Ab[(size_t)(m0 + r) * lda + k0 + c4];
            *(float4*)&As[r][c4] = v;
        }
        // ---- load B tile into Bs[n][k] ----
        if (!TRANSB) {
            #pragma unroll
            for (int i = tid; i < BN * BK / 4; i += NTH) {
                int r  = i / (BK / 4);
                int c4 = (i % (BK / 4)) * 4;
                float4 v = *(const float4*)&Bb[(size_t)(n0 + r) * ldb + k0 + c4];
                *(float4*)&Bs[r][c4] = v;
            }
        } else {
            #pragma unroll
            for (int i = tid; i < BN * BK; i += NTH) {
                int kk = i / BN;
                int nn = i % BN;
                Bs[nn][kk] = Bb[(size_t)(k0 + kk) * ldb + n0 + nn];
            }
        }
        __syncthreads();

        // ---- compute: BK/8 k-steps of m16n8k8 ----
        #pragma unroll
        for (int ks = 0; ks < BK / 8; ks++) {
            const int k8 = ks * 8;
            uint32_t af[4][4];
            uint32_t bf[4][2];
            #pragma unroll
            for (int mf = 0; mf < 4; mf++) {
                int r = wm * 64 + mf * 16 + g;
                af[mf][0] = f2tf(As[r    ][k8 + t    ]);
                af[mf][1] = f2tf(As[r + 8][k8 + t    ]);
                af[mf][2] = f2tf(As[r    ][k8 + t + 4]);
                af[mf][3] = f2tf(As[r + 8][k8 + t + 4]);
            }
            #pragma unroll
            for (int nf = 0; nf < 4; nf++) {
                int c = wn * 32 + nf * 8 + g;
                bf[nf][0] = f2tf(Bs[c][k8 + t    ]);
                bf[nf][1] = f2tf(Bs[c][k8 + t + 4]);
            }
            #pragma unroll
            for (int mf = 0; mf < 4; mf++)
                #pragma unroll
                for (int nf = 0; nf < 4; nf++)
                    mma_tf32(acc[mf][nf], af[mf], bf[nf]);
        }
        __syncthreads();
    }

    // ---- epilogue ----
    #pragma unroll
    for (int mf = 0; mf < 4; mf++) {
        #pragma unroll
        for (int nf = 0; nf < 4; nf++) {
            int r = m0 + wm * 64 + mf * 16 + g;
            int c = n0 + wn * 32 + nf * 8 + 2 * t;
            float b0 = 0.f, b1 = 0.f;
            if (HAS_BIAS) { b0 = bias[c]; b1 = bias[c + 1]; }
            Cb[(size_t)r       * ldc + c    ] = alpha * acc[mf][nf][0] + b0;
            Cb[(size_t)r       * ldc + c + 1] = alpha * acc[mf][nf][1] + b1;
            Cb[(size_t)(r + 8) * ldc + c    ] = alpha * acc[mf][nf][2] + b0;
            Cb[(size_t)(r + 8) * ldc + c + 1] = alpha * acc[mf][nf][3] + b1;
        }
    }
}

// ---------------- RoPE (in place on Q and K) ----------------
// i layout: b*(2048*16*32) + n*(16*32) + h*32 + ii
__global__ void rope_kernel(float* __restrict__ Q, float* __restrict__ K,
                            const float* __restrict__ cosb, const float* __restrict__ sinb)
{
    int i  = blockIdx.x * blockDim.x + threadIdx.x;   // 2*2048*16*32 total
    int ii = i & 31;
    int h  = (i >> 5) & 15;
    int n  = (i >> 9) & 2047;
    int b  = i >> 20;
    size_t base = ((size_t)(b * SEQ + n)) * DIM + h * HDIM + 2 * ii;
    float cv = cosb[n * 32 + ii];
    float sv = sinb[n * 32 + ii];

    float q1 = Q[base], q2 = Q[base + 1];
    Q[base]     = q1 * cv - q2 * sv;
    Q[base + 1] = q1 * sv + q2 * cv;
    float k1 = K[base], k2 = K[base + 1];
    K[base]     = k1 * cv - k2 * sv;
    K[base + 1] = k1 * sv + k2 * cv;
}

// ---------------- row softmax over 2048 cols, in place ----------------
__global__ void softmax_kernel(float* __restrict__ S)
{
    const size_t base = (size_t)blockIdx.x * SEQ;
    const int tid = threadIdx.x;   // 256
    float v[8];
    float mx = -1e30f;
    #pragma unroll
    for (int i = 0; i < 8; i++) {
        v[i] = S[base + tid + 256 * i];
        mx = fmaxf(mx, v[i]);
    }
    #pragma unroll
    for (int o = 16; o > 0; o >>= 1)
        mx = fmaxf(mx, __shfl_xor_sync(0xffffffffu, mx, o));

    __shared__ float rm[8], rs[8];
    if ((tid & 31) == 0) rm[tid >> 5] = mx;
    __syncthreads();
    mx = rm[0];
    #pragma unroll
    for (int w = 1; w < 8; w++) mx = fmaxf(mx, rm[w]);

    float s = 0.f;
    #pragma unroll
    for (int i = 0; i < 8; i++) {
        v[i] = __expf(v[i] - mx);
        s += v[i];
    }
    #pragma unroll
    for (int o = 16; o > 0; o >>= 1)
        s += __shfl_xor_sync(0xffffffffu, s, o);
    if ((tid & 31) == 0) rs[tid >> 5] = s;
    __syncthreads();
    s = 0.f;
    #pragma unroll
    for (int w = 0; w < 8; w++) s += rs[w];

    const float inv = 1.f / s;
    #pragma unroll
    for (int i = 0; i < 8; i++)
        S[base + tid + 256 * i] = v[i] * inv;
}

// ---------------- launch ----------------
extern "C" void kernel_launch(void* const* d_in, const int* in_sizes, int n_in,
                              void* d_out, int out_size)
{
    const float* x   = (const float*)d_in[0];
    const float* fc  = (const float*)d_in[1];
    const float* fs  = (const float*)d_in[2];
    const float* Wq  = (const float*)d_in[3];
    const float* Wk  = (const float*)d_in[4];
    const float* Wv  = (const float*)d_in[5];
    const float* Wo  = (const float*)d_in[6];
    const float* bo  = (const float*)d_in[7];
    float* out = (float*)d_out;

    float *Q, *K, *V, *O, *S;
    cudaGetSymbolAddress((void**)&Q, g_Q);
    cudaGetSymbolAddress((void**)&K, g_K);
    cudaGetSymbolAddress((void**)&V, g_V);
    cudaGetSymbolAddress((void**)&O, g_O);
    cudaGetSymbolAddress((void**)&S, g_S);

    // 1) Q/K/V projections: [4096,1024] = x[4096,1024] @ W^T
    dim3 gProj(DIM / 128, MROWS / 128, 1);  // (8, 32, 1)
    gemm_tf32<128, 128, 16, false, false><<<gProj, 256>>>(
        x, Wq, Q, DIM, DIM, DIM, DIM, 0, 0, 0, 0, 0, 0, 1.0f, nullptr);
    gemm_tf32<128, 128, 16, false, false><<<gProj, 256>>>(
        x, Wk, K, DIM, DIM, DIM, DIM, 0, 0, 0, 0, 0, 0, 1.0f, nullptr);
    gemm_tf32<128, 128, 16, false, false><<<gProj, 256>>>(
        x, Wv, V, DIM, DIM, DIM, DIM, 0, 0, 0, 0, 0, 0, 1.0f, nullptr);

    // 2) RoPE on Q and K
    rope_kernel<<<(BATCH * SEQ * HEADS * 32) / 256, 256>>>(Q, K, fc, fs);

    // 3) scores: per (b,h)  S = (Q_bh @ K_bh^T) * 1/sqrt(64)
    dim3 gScore(SEQ / 128, SEQ / 128, BH);  // (16, 16, 32)
    gemm_tf32<128, 128, 16, false, false><<<gScore, 256>>>(
        Q, K, S, HDIM, DIM, DIM, SEQ,
        (long long)SEQ * DIM, HDIM,
        (long long)SEQ * DIM, HDIM,
        (long long)HEADS * SEQ * SEQ, (long long)SEQ * SEQ,
        0.125f, nullptr);

    // 4) softmax rows
    softmax_kernel<<<BH * SEQ, 256>>>(S);

    // 5) O_bh = P @ V_bh   (V is (k=key, n=d) row-major -> TRANSB)
    dim3 gPV(1, SEQ / 128, BH);  // (1, 16, 32)
    gemm_tf32<128, 64, 16, true, false><<<gPV, 128>>>(
        S, V, O, SEQ, SEQ, DIM, DIM,
        (long long)HEADS * SEQ * SEQ, (long long)SEQ * SEQ,
        (long long)SEQ * DIM, HDIM,
        (long long)SEQ * DIM, HDIM,
        1.0f, nullptr);

    // 6) out = O @ Wo^T + bo
    dim3 gOut(DIM / 128, MROWS / 128, 1);
    gemm_tf32<128, 128, 16, false, true><<<gOut, 256>>>(
        O, Wo, out, DIM, DIM, DIM, DIM, 0, 0, 0, 0, 0, 0, 1.0f, bo);
}

// round 2
// speedup vs baseline: 2.1720x; 2.1720x over previous
#include <cuda_runtime.h>
#include <cuda_bf16.h>
#include <cstdint>

// Problem constants
#define BATCH 2
#define SEQ   2048
#define DIM   1024
#define HEADS 16
#define HDIM  64
#define MROWS (BATCH * SEQ)          // 4096
#define BH    (BATCH * HEADS)        // 32

// ---------------- scratch ----------------
__device__ float g_Q[(size_t)MROWS * DIM];
__device__ float g_K[(size_t)MROWS * DIM];
__device__ float g_V[(size_t)MROWS * DIM];
__device__ float g_O[(size_t)MROWS * DIM];

// ---------------- tf32 helpers ----------------
__device__ __forceinline__ uint32_t f2tf(float f) {
    uint32_t u;
    asm("cvt.rna.tf32.f32 %0, %1;" : "=r"(u) : "f"(f));
    return u;
}

__device__ __forceinline__ void mma_tf32(float c[4], const uint32_t a[4], const uint32_t b[2]) {
    asm volatile(
        "mma.sync.aligned.m16n8k8.row.col.f32.tf32.tf32.f32 "
        "{%0,%1,%2,%3}, {%4,%5,%6,%7}, {%8,%9}, {%0,%1,%2,%3};\n"
        : "+f"(c[0]), "+f"(c[1]), "+f"(c[2]), "+f"(c[3])
        : "r"(a[0]), "r"(a[1]), "r"(a[2]), "r"(a[3]), "r"(b[0]), "r"(b[1]));
}

// ---------------- generic tf32 GEMM (C = alpha * A @ B^T + bias) ----------------
// A row-major [M,K], B row-major [N,K] (i.e. weight W[n][k]), C row-major [M,N].
template<int BM, int BN, int BK, bool HAS_BIAS>
__global__ void __launch_bounds__(256)
gemm_tf32(const float* __restrict__ A, const float* __restrict__ B, float* __restrict__ C,
          int Kdim, int ld, float alpha, const float* __restrict__ bias)
{
    constexpr int WN  = BN / 32;           // warps along n
    constexpr int WM  = BM / 64;           // warps along m
    constexpr int NTH = WM * WN * 32;
    constexpr int KS  = BK + 4;

    const int m0 = blockIdx.y * BM;
    const int n0 = blockIdx.x * BN;

    const int tid  = threadIdx.x;
    const int warp = tid >> 5;
    const int lane = tid & 31;
    const int g    = lane >> 2;
    const int t    = lane & 3;
    const int wm   = warp / WN;
    const int wn   = warp % WN;

    __shared__ uint32_t As[BM][KS];
    __shared__ uint32_t Bs[BN][KS];

    float acc[4][4][4] = {};

    for (int k0 = 0; k0 < Kdim; k0 += BK) {
        #pragma unroll
        for (int i = tid; i < BM * BK / 4; i += NTH) {
            int r  = i / (BK / 4);
            int c4 = (i % (BK / 4)) * 4;
            float4 v = *(const float4*)&A[(size_t)(m0 + r) * ld + k0 + c4];
            uint32_t* d = &As[r][c4];
            d[0] = f2tf(v.x); d[1] = f2tf(v.y); d[2] = f2tf(v.z); d[3] = f2tf(v.w);
        }
        #pragma unroll
        for (int i = tid; i < BN * BK / 4; i += NTH) {
            int r  = i / (BK / 4);
            int c4 = (i % (BK / 4)) * 4;
            float4 v = *(const float4*)&B[(size_t)(n0 + r) * ld + k0 + c4];
            uint32_t* d = &Bs[r][c4];
            d[0] = f2tf(v.x); d[1] = f2tf(v.y); d[2] = f2tf(v.z); d[3] = f2tf(v.w);
        }
        __syncthreads();

        #pragma unroll
        for (int ks = 0; ks < BK / 8; ks++) {
            const int k8 = ks * 8;
            uint32_t af[4][4];
            uint32_t bf[4][2];
            #pragma unroll
            for (int mf = 0; mf < 4; mf++) {
                int r = wm * 64 + mf * 16 + g;
                af[mf][0] = As[r    ][k8 + t    ];
                af[mf][1] = As[r + 8][k8 + t    ];
                af[mf][2] = As[r    ][k8 + t + 4];
                af[mf][3] = As[r + 8][k8 + t + 4];
            }
            #pragma unroll
            for (int nf = 0; nf < 4; nf++) {
                int c = wn * 32 + nf * 8 + g;
                bf[nf][0] = Bs[c][k8 + t    ];
                bf[nf][1] = Bs[c][k8 + t + 4];
            }
            #pragma unroll
            for (int mf = 0; mf < 4; mf++)
                #pragma unroll
                for (int nf = 0; nf < 4; nf++)
                    mma_tf32(acc[mf][nf], af[mf], bf[nf]);
        }
        __syncthreads();
    }

    #pragma unroll
    for (int mf = 0; mf < 4; mf++) {
        #pragma unroll
        for (int nf = 0; nf < 4; nf++) {
            int r = m0 + wm * 64 + mf * 16 + g;
            int c = n0 + wn * 32 + nf * 8 + 2 * t;
            float b0 = 0.f, b1 = 0.f;
            if (HAS_BIAS) { b0 = bias[c]; b1 = bias[c + 1]; }
            float2 v0 = make_float2(alpha * acc[mf][nf][0] + b0, alpha * acc[mf][nf][1] + b1);
            float2 v1 = make_float2(alpha * acc[mf][nf][2] + b0, alpha * acc[mf][nf][3] + b1);
            *(float2*)&C[(size_t)r       * ld + c] = v0;
            *(float2*)&C[(size_t)(r + 8) * ld + c] = v1;
        }
    }
}

// ---------------- RoPE (in place on Q and K) ----------------
__global__ void rope_kernel(float* __restrict__ Q, float* __restrict__ K,
                            const float* __restrict__ cosb, const float* __restrict__ sinb)
{
    int i  = blockIdx.x * blockDim.x + threadIdx.x;
    int ii = i & 31;
    int h  = (i >> 5) & 15;
    int n  = (i >> 9) & 2047;
    int b  = i >> 20;
    size_t base = ((size_t)(b * SEQ + n)) * DIM + h * HDIM + 2 * ii;
    float cv = cosb[n * 32 + ii];
    float sv = sinb[n * 32 + ii];

    float q1 = Q[base], q2 = Q[base + 1];
    Q[base]     = q1 * cv - q2 * sv;
    Q[base + 1] = q1 * sv + q2 * cv;
    float k1 = K[base], k2 = K[base + 1];
    K[base]     = k1 * cv - k2 * sv;
    K[base + 1] = k1 * sv + k2 * cv;
}

// ---------------- fused flash attention ----------------
// grid (SEQ/128, BH), 256 threads. Each warp owns 16 query rows x all 128 keys.
#define QS_STRIDE 68
#define KS_STRIDE 68
#define VS_STRIDE 72

__global__ void __launch_bounds__(256, 1)
flash_attn(const float* __restrict__ Q, const float* __restrict__ K,
           const float* __restrict__ V, float* __restrict__ O)
{
    extern __shared__ uint32_t sm[];
    uint32_t* Qs = sm;                          // 128 * 68
    uint32_t* Ks = Qs + 128 * QS_STRIDE;        // 128 * 68
    uint32_t* Vs = Ks + 128 * KS_STRIDE;        // 128 * 72

    const int bh = blockIdx.y;
    const int b  = bh >> 4;
    const int h  = bh & 15;
    const int q0 = blockIdx.x * 128;

    const int tid  = threadIdx.x;
    const int warp = tid >> 5;
    const int lane = tid & 31;
    const int g    = lane >> 2;
    const int t    = lane & 3;
    const int wrow = warp * 16;

    const size_t base = ((size_t)b * SEQ) * DIM + (size_t)h * HDIM;

    // load Q tile (128 x 64) -> tf32 smem
    #pragma unroll
    for (int i = tid; i < 128 * 16; i += 256) {
        int r = i >> 4, c4 = (i & 15) << 2;
        float4 v = *(const float4*)&Q[base + (size_t)(q0 + r) * DIM + c4];
        uint32_t* d = &Qs[r * QS_STRIDE + c4];
        d[0] = f2tf(v.x); d[1] = f2tf(v.y); d[2] = f2tf(v.z); d[3] = f2tf(v.w);
    }

    float m0 = -1e30f, m1 = -1e30f, l0 = 0.f, l1 = 0.f;
    float oacc[8][4] = {};

    for (int j0 = 0; j0 < SEQ; j0 += 128) {
        // load K,V tiles
        #pragma unroll
        for (int i = tid; i < 128 * 16; i += 256) {
            int r = i >> 4, c4 = (i & 15) << 2;
            float4 kv = *(const float4*)&K[base + (size_t)(j0 + r) * DIM + c4];
            uint32_t* kd = &Ks[r * KS_STRIDE + c4];
            kd[0] = f2tf(kv.x); kd[1] = f2tf(kv.y); kd[2] = f2tf(kv.z); kd[3] = f2tf(kv.w);
            float4 vv = *(const float4*)&V[base + (size_t)(j0 + r) * DIM + c4];
            uint32_t* vd = &Vs[r * VS_STRIDE + c4];
            vd[0] = f2tf(vv.x); vd[1] = f2tf(vv.y); vd[2] = f2tf(vv.z); vd[3] = f2tf(vv.w);
        }
        __syncthreads();

        // ---- S = Q @ K^T (warp: 16 rows x 128 cols) ----
        float sacc[16][4];
        #pragma unroll
        for (int nf = 0; nf < 16; nf++)
            #pragma unroll
            for (int r = 0; r < 4; r++) sacc[nf][r] = 0.f;

        #pragma unroll
        for (int ks = 0; ks < 8; ks++) {
            const int k8 = ks * 8;
            uint32_t a[4];
            a[0] = Qs[(wrow + g    ) * QS_STRIDE + k8 + t    ];
            a[1] = Qs[(wrow + g + 8) * QS_STRIDE + k8 + t    ];
            a[2] = Qs[(wrow + g    ) * QS_STRIDE + k8 + t + 4];
            a[3] = Qs[(wrow + g + 8) * QS_STRIDE + k8 + t + 4];
            #pragma unroll
            for (int nf = 0; nf < 16; nf++) {
                uint32_t bb[2];
                bb[0] = Ks[(nf * 8 + g) * KS_STRIDE + k8 + t    ];
                bb[1] = Ks[(nf * 8 + g) * KS_STRIDE + k8 + t + 4];
                mma_tf32(sacc[nf], a, bb);
            }
        }

        // ---- online softmax ----
        float tm0 = -1e30f, tm1 = -1e30f;
        #pragma unroll
        for (int nf = 0; nf < 16; nf++) {
            #pragma unroll
            for (int r = 0; r < 4; r++) sacc[nf][r] *= 0.125f;
            tm0 = fmaxf(tm0, fmaxf(sacc[nf][0], sacc[nf][1]));
            tm1 = fmaxf(tm1, fmaxf(sacc[nf][2], sacc[nf][3]));
        }
        tm0 = fmaxf(tm0, __shfl_xor_sync(0xffffffffu, tm0, 1));
        tm0 = fmaxf(tm0, __shfl_xor_sync(0xffffffffu, tm0, 2));
        tm1 = fmaxf(tm1, __shfl_xor_sync(0xffffffffu, tm1, 1));
        tm1 = fmaxf(tm1, __shfl_xor_sync(0xffffffffu, tm1, 2));

        float nm0 = fmaxf(m0, tm0), nm1 = fmaxf(m1, tm1);
        float al0 = __expf(m0 - nm0), al1 = __expf(m1 - nm1);
        m0 = nm0; m1 = nm1;

        float rs0 = 0.f, rs1 = 0.f;
        uint32_t p[16][4];
        #pragma unroll
        for (int nf = 0; nf < 16; nf++) {
            float e0 = __expf(sacc[nf][0] - m0);
            float e1 = __expf(sacc[nf][1] - m0);
            float e2 = __expf(sacc[nf][2] - m1);
            float e3 = __expf(sacc[nf][3] - m1);
            rs0 += e0 + e1; rs1 += e2 + e3;
            p[nf][0] = f2tf(e0); p[nf][1] = f2tf(e1);
            p[nf][2] = f2tf(e2); p[nf][3] = f2tf(e3);
        }
        rs0 += __shfl_xor_sync(0xffffffffu, rs0, 1);
        rs0 += __shfl_xor_sync(0xffffffffu, rs0, 2);
        rs1 += __shfl_xor_sync(0xffffffffu, rs1, 1);
        rs1 += __shfl_xor_sync(0xffffffffu, rs1, 2);
        l0 = l0 * al0 + rs0;
        l1 = l1 * al1 + rs1;

        #pragma unroll
        for (int nf = 0; nf < 8; nf++) {
            oacc[nf][0] *= al0; oacc[nf][1] *= al0;
            oacc[nf][2] *= al1; oacc[nf][3] *= al1;
        }

        // ---- O += P @ V  (P in registers; C-layout -> A-layout via shuffles) ----
        const int src0 = (g << 2) | (t >> 1);
        const int src1 = src0 + 2;
        const bool odd = (t & 1);
        #pragma unroll
        for (int ks = 0; ks < 16; ks++) {
            uint32_t x0 = __shfl_sync(0xffffffffu, p[ks][0], src0);
            uint32_t x1 = __shfl_sync(0xffffffffu, p[ks][1], src0);
            uint32_t x2 = __shfl_sync(0xffffffffu, p[ks][2], src0);
            uint32_t x3 = __shfl_sync(0xffffffffu, p[ks][3], src0);
            uint32_t y0 = __shfl_sync(0xffffffffu, p[ks][0], src1);
            uint32_t y1 = __shfl_sync(0xffffffffu, p[ks][1], src1);
            uint32_t y2 = __shfl_sync(0xffffffffu, p[ks][2], src1);
            uint32_t y3 = __shfl_sync(0xffffffffu, p[ks][3], src1);
            uint32_t a[4];
            a[0] = odd ? x1 : x0;
            a[1] = odd ? x3 : x2;
            a[2] = odd ? y1 : y0;
            a[3] = odd ? y3 : y2;
            const int k8 = ks * 8;
            #pragma unroll
            for (int nf = 0; nf < 8; nf++) {
                uint32_t bb[2];
                bb[0] = Vs[(k8 + t    ) * VS_STRIDE + nf * 8 + g];
                bb[1] = Vs[(k8 + t + 4) * VS_STRIDE + nf * 8 + g];
                mma_tf32(oacc[nf], a, bb);
            }
        }
        __syncthreads();
    }

    // ---- finalize: O /= l, write ----
    const float inv0 = 1.f / l0, inv1 = 1.f / l1;
    #pragma unroll
    for (int nf = 0; nf < 8; nf++) {
        int r0 = q0 + wrow + g;
        int c  = nf * 8 + 2 * t;
        float2 v0 = make_float2(oacc[nf][0] * inv0, oacc[nf][1] * inv0);
        float2 v1 = make_float2(oacc[nf][2] * inv1, oacc[nf][3] * inv1);
        *(float2*)&O[base + (size_t)r0 * DIM + c]       = v0;
        *(float2*)&O[base + (size_t)(r0 + 8) * DIM + c] = v1;
    }
}

// ---------------- launch ----------------
extern "C" void kernel_launch(void* const* d_in, const int* in_sizes, int n_in,
                              void* d_out, int out_size)
{
    const float* x   = (const float*)d_in[0];
    const float* fc  = (const float*)d_in[1];
    const float* fs  = (const float*)d_in[2];
    const float* Wq  = (const float*)d_in[3];
    const float* Wk  = (const float*)d_in[4];
    const float* Wv  = (const float*)d_in[5];
    const float* Wo  = (const float*)d_in[6];
    const float* bo  = (const float*)d_in[7];
    float* out = (float*)d_out;

    float *Q, *K, *V, *O;
    cudaGetSymbolAddress((void**)&Q, g_Q);
    cudaGetSymbolAddress((void**)&K, g_K);
    cudaGetSymbolAddress((void**)&V, g_V);
    cudaGetSymbolAddress((void**)&O, g_O);

    // 1) Q/K/V projections
    dim3 gProj(DIM / 128, MROWS / 128, 1);
    gemm_tf32<128, 128, 32, false><<<gProj, 256>>>(x, Wq, Q, DIM, DIM, 1.0f, nullptr);
    gemm_tf32<128, 128, 32, false><<<gProj, 256>>>(x, Wk, K, DIM, DIM, 1.0f, nullptr);
    gemm_tf32<128, 128, 32, false><<<gProj, 256>>>(x, Wv, V, DIM, DIM, 1.0f, nullptr);

    // 2) RoPE on Q and K
    rope_kernel<<<(BATCH * SEQ * HEADS * 32) / 256, 256>>>(Q, K, fc, fs);

    // 3) fused attention
    const int fa_smem = (128 * QS_STRIDE + 128 * KS_STRIDE + 128 * VS_STRIDE) * 4;
    cudaFuncSetAttribute(flash_attn, cudaFuncAttributeMaxDynamicSharedMemorySize, fa_smem);
    dim3 gFA(SEQ / 128, BH, 1);
    flash_attn<<<gFA, 256, fa_smem>>>(Q, K, V, O);

    // 4) out = O @ Wo^T + bo
    dim3 gOut(DIM / 128, MROWS / 128, 1);
    gemm_tf32<128, 128, 32, true><<<gOut, 256>>>(O, Wo, out, DIM, DIM, 1.0f, bo);
}